// round 11
// baseline (speedup 1.0000x reference)
#include <cuda_runtime.h>
#include <cuda_fp16.h>
#include <cstdint>

#define TOTAL    8192
#define HIDDEN   1280
#define HEADS    16
#define HEAD_DIM 80
#define NCHUNK   8
#define CHUNK_L  1024
#define QKVN     3840
#define SCALE    0.11180339887498949f  /* 80^-0.5 */

// ---------------- device scratch (no allocs allowed) ----------------
__device__ float  g_qkv [(size_t)TOTAL * QKVN];            // q,k fp32 (v unused)
__device__ __half g_V16 [(size_t)TOTAL * HIDDEN];          // fp16 v (GEMM epilogue)
__device__ __half g_Aq  [(size_t)TOTAL * HIDDEN];          // fp16(x)
__device__ __half g_Ap  [(size_t)TOTAL * HIDDEN];          // fp16(attn)
__device__ __half g_Bq  [(size_t)QKVN  * HIDDEN];          // fp16(w_qkv)^T
__device__ __half g_Bp  [(size_t)HIDDEN* HIDDEN];          // fp16(w_proj)^T
__device__ __half g_Q1 [(size_t)TOTAL * HEADS * HEAD_DIM]; // fp16 roped q
__device__ __half g_K1 [(size_t)TOTAL * HEADS * HEAD_DIM]; // fp16 roped k
__device__ __half g_Vt [(size_t)NCHUNK * HEADS * HEAD_DIM * CHUNK_L];

// ---------------- PTX helpers ----------------
__device__ __forceinline__ uint32_t smem_u32(const void* p) {
    uint32_t a;
    asm("{ .reg .u64 t; cvta.to.shared.u64 t, %1; cvt.u32.u64 %0, t; }"
        : "=r"(a) : "l"(p));
    return a;
}
__device__ __forceinline__ void ldsm_x4(uint32_t* r, uint32_t addr) {
    asm volatile("ldmatrix.sync.aligned.m8n8.x4.shared.b16 {%0,%1,%2,%3}, [%4];"
                 : "=r"(r[0]), "=r"(r[1]), "=r"(r[2]), "=r"(r[3]) : "r"(addr));
}
__device__ __forceinline__ void mma_16816(float* c, const uint32_t* a,
                                          const uint32_t* b) {
    asm volatile(
        "mma.sync.aligned.m16n8k16.row.col.f32.f16.f16.f32 "
        "{%0,%1,%2,%3}, {%4,%5,%6,%7}, {%8,%9}, {%0,%1,%2,%3};"
        : "+f"(c[0]), "+f"(c[1]), "+f"(c[2]), "+f"(c[3])
        : "r"(a[0]), "r"(a[1]), "r"(a[2]), "r"(a[3]), "r"(b[0]), "r"(b[1]));
}
__device__ __forceinline__ void cp16(uint32_t dst, const void* src) {
    asm volatile("cp.async.cg.shared.global [%0], [%1], 16;"
                 :: "r"(dst), "l"(src));
}
__device__ __forceinline__ void cp_commit() {
    asm volatile("cp.async.commit_group;" ::: "memory");
}
template <int W>
__device__ __forceinline__ void cp_wait() {
    asm volatile("cp.async.wait_group %0;" :: "n"(W) : "memory");
}
__device__ __forceinline__ uint32_t pack2h(__half lo, __half hi) {
    return (uint32_t)__half_as_ushort(lo) |
           ((uint32_t)__half_as_ushort(hi) << 16);
}

// ---------------------------------------------------------------------------
// Tensor-core GEMM: C[8192, N] = A * B^T + bias. If Vout != nullptr, columns
// >= 2*HIDDEN are written as fp16 to Vout[t][col-2*HIDDEN] instead of C.
// ---------------------------------------------------------------------------
#define BK     32
#define NST    3
#define LDAE   40
#define ROWB   (LDAE * 2)
#define STAGEB (128 * ROWB)
#define BOFF   (NST * STAGEB)
#define GSMEM  (2 * NST * STAGEB)

__global__ __launch_bounds__(128, 2) void gemm_fp16_mma(
    const __half* __restrict__ A, const __half* __restrict__ B,
    const float* __restrict__ bias, float* __restrict__ C,
    __half* __restrict__ Vout, int N, int K)
{
    extern __shared__ char sm[];
    const int tid  = threadIdx.x;
    const int wid  = tid >> 5;
    const int lane = tid & 31;
    const int m0   = blockIdx.y * 128;
    const int n0   = blockIdx.x * 128;
    const int wm   = wid & 1;
    const int wn   = wid >> 1;

    uint32_t aDst[4], bDst[4];
    const __half *aS[4], *bS[4];
#pragma unroll
    for (int p = 0; p < 4; p++) {
        int u  = tid + p * 128;
        int r  = u >> 2;
        int ch = (u & 3) * 8;
        aDst[p] = smem_u32(sm + r * ROWB + ch * 2);
        bDst[p] = aDst[p] + BOFF;
        aS[p]   = A + (size_t)(m0 + r) * K + ch;
        bS[p]   = B + (size_t)(n0 + r) * K + ch;
    }

    float acc[4][8][4];
#pragma unroll
    for (int mt = 0; mt < 4; mt++)
#pragma unroll
        for (int nt = 0; nt < 8; nt++)
#pragma unroll
            for (int v = 0; v < 4; v++) acc[mt][nt][v] = 0.0f;

    const int lrow  = lane & 15;
    const int lcolb = ((lane >> 4) << 3) * 2;
    uint32_t aAddr[4], bAddr[4];
#pragma unroll
    for (int mt = 0; mt < 4; mt++)
        aAddr[mt] = smem_u32(sm + (wm * 64 + mt * 16 + lrow) * ROWB + lcolb);
#pragma unroll
    for (int np = 0; np < 4; np++)
        bAddr[np] = smem_u32(sm + BOFF + (wn * 64 + np * 16 + lrow) * ROWB + lcolb);

#pragma unroll
    for (int s = 0; s < 2; s++) {
#pragma unroll
        for (int p = 0; p < 4; p++) {
            cp16(aDst[p] + s * STAGEB, aS[p] + s * BK);
            cp16(bDst[p] + s * STAGEB, bS[p] + s * BK);
        }
        cp_commit();
    }

    const int NKB = K / BK;
    for (int kb = 0; kb < NKB; kb++) {
        cp_wait<1>();
        __syncthreads();

        const int nxt = kb + 2;
        if (nxt < NKB) {
            const uint32_t so = (uint32_t)(nxt % NST) * STAGEB;
#pragma unroll
            for (int p = 0; p < 4; p++) {
                cp16(aDst[p] + so, aS[p] + nxt * BK);
                cp16(bDst[p] + so, bS[p] + nxt * BK);
            }
        }
        cp_commit();

        const uint32_t base = (uint32_t)(kb % NST) * STAGEB;
#pragma unroll
        for (int ks = 0; ks < 2; ks++) {
            const uint32_t ko = base + ks * 32;
            uint32_t af[4][4];
#pragma unroll
            for (int mt = 0; mt < 4; mt++)
                ldsm_x4(af[mt], aAddr[mt] + ko);
            uint32_t bf[8][2];
#pragma unroll
            for (int np = 0; np < 4; np++) {
                uint32_t r[4];
                ldsm_x4(r, bAddr[np] + ko);
                bf[2 * np][0]     = r[0]; bf[2 * np][1]     = r[2];
                bf[2 * np + 1][0] = r[1]; bf[2 * np + 1][1] = r[3];
            }
#pragma unroll
            for (int mt = 0; mt < 4; mt++)
#pragma unroll
                for (int nt = 0; nt < 8; nt++)
                    mma_16816(acc[mt][nt], af[mt], bf[nt]);
        }
    }

    const int cr = lane >> 2;
    const int cc = (lane & 3) * 2;
#pragma unroll
    for (int mt = 0; mt < 4; mt++) {
        const int r0 = m0 + wm * 64 + mt * 16 + cr;
#pragma unroll
        for (int nt = 0; nt < 8; nt++) {
            const int col = n0 + wn * 64 + nt * 8 + cc;
            const float b0 = __ldg(&bias[col]);
            const float b1 = __ldg(&bias[col + 1]);
            float o00 = acc[mt][nt][0] + b0, o01 = acc[mt][nt][1] + b1;
            float o10 = acc[mt][nt][2] + b0, o11 = acc[mt][nt][3] + b1;
            if (Vout != nullptr && col >= 2 * HIDDEN) {
                const int vc = col - 2 * HIDDEN;
                *(uint32_t*)&Vout[(size_t)r0 * HIDDEN + vc] =
                    pack2h(__float2half_rn(o00), __float2half_rn(o01));
                *(uint32_t*)&Vout[(size_t)(r0 + 8) * HIDDEN + vc] =
                    pack2h(__float2half_rn(o10), __float2half_rn(o11));
            } else {
                float2 v0, v1;
                v0.x = o00; v0.y = o01;
                v1.x = o10; v1.y = o11;
                *(float2*)&C[(size_t)r0 * N + col]       = v0;
                *(float2*)&C[(size_t)(r0 + 8) * N + col] = v1;
            }
        }
    }
}

// ---------------------------------------------------------------------------
// Plain fp16 conversion of activations: X[MK] fp32 -> O[MK] fp16
// ---------------------------------------------------------------------------
__global__ __launch_bounds__(256) void convert_A(
    const float* __restrict__ X, __half* __restrict__ O, int MK)
{
    int idx = (blockIdx.x * 256 + threadIdx.x) * 4;
    if (idx >= MK) return;
    float4 v = *(const float4*)&X[idx];
    uint32_t p0 = pack2h(__float2half_rn(v.x), __float2half_rn(v.y));
    uint32_t p1 = pack2h(__float2half_rn(v.z), __float2half_rn(v.w));
    *(uint2*)&O[idx] = make_uint2(p0, p1);
}

// ---------------------------------------------------------------------------
// fp16 weight transpose: W[K,N] fp32 -> O[N,K]
// ---------------------------------------------------------------------------
__global__ __launch_bounds__(256) void convert_B1(
    const float* __restrict__ W, __half* __restrict__ O, int K, int N)
{
    __shared__ float t[32][33];
    const int k0 = blockIdx.y * 32, n0 = blockIdx.x * 32;
    const int tx = threadIdx.x, ty = threadIdx.y;
#pragma unroll
    for (int i = 0; i < 32; i += 8)
        t[ty + i][tx] = W[(size_t)(k0 + ty + i) * N + n0 + tx];
    __syncthreads();
#pragma unroll
    for (int i = 0; i < 32; i += 8) {
        int n = n0 + ty + i, k = k0 + tx;
        O[(size_t)n * K + k] = __float2half_rn(t[tx][ty + i]);
    }
}

// ---------------------------------------------------------------------------
// RoPE + fp16 conversion of q,k, vectorized x4 (q pre-scaled by hd^-0.5).
// One thread handles 4 consecutive d values of one (t, h).
// ---------------------------------------------------------------------------
__global__ __launch_bounds__(256) void rope_split(
    const float* __restrict__ cosp, const float* __restrict__ sinp)
{
    int idx = blockIdx.x * blockDim.x + threadIdx.x;
    const int total = TOTAL * HEADS * 10;
    if (idx >= total) return;
    int b = idx % 10;
    int h = (idx / 10) % HEADS;
    int t = idx / (10 * HEADS);
    int d0 = b * 4;

    const float* row = g_qkv + (size_t)t * QKVN;
    int qi = h * HEAD_DIM + d0;

    float4 q1 = *(const float4*)&row[qi];
    float4 q2 = *(const float4*)&row[qi + 40];
    float4 k1 = *(const float4*)&row[HIDDEN + qi];
    float4 k2 = *(const float4*)&row[HIDDEN + qi + 40];
    float4 c1 = *(const float4*)&cosp[t * HEAD_DIM + d0];
    float4 s1 = *(const float4*)&sinp[t * HEAD_DIM + d0];
    float4 c2 = *(const float4*)&cosp[t * HEAD_DIM + d0 + 40];
    float4 s2 = *(const float4*)&sinp[t * HEAD_DIM + d0 + 40];

    float rq1[4], rq2[4], rk1[4], rk2[4];
    const float* q1a = &q1.x; const float* q2a = &q2.x;
    const float* k1a = &k1.x; const float* k2a = &k2.x;
    const float* c1a = &c1.x; const float* s1a = &s1.x;
    const float* c2a = &c2.x; const float* s2a = &s2.x;
#pragma unroll
    for (int i = 0; i < 4; i++) {
        rq1[i] = (q1a[i] * c1a[i] - q2a[i] * s1a[i]) * SCALE;
        rq2[i] = (q2a[i] * c2a[i] + q1a[i] * s2a[i]) * SCALE;
        rk1[i] = k1a[i] * c1a[i] - k2a[i] * s1a[i];
        rk2[i] = k2a[i] * c2a[i] + k1a[i] * s2a[i];
    }

    __half* Q = g_Q1 + ((size_t)t * HEADS + h) * HEAD_DIM;
    __half* K = g_K1 + ((size_t)t * HEADS + h) * HEAD_DIM;
    *(uint2*)&Q[d0] = make_uint2(
        pack2h(__float2half_rn(rq1[0]), __float2half_rn(rq1[1])),
        pack2h(__float2half_rn(rq1[2]), __float2half_rn(rq1[3])));
    *(uint2*)&Q[d0 + 40] = make_uint2(
        pack2h(__float2half_rn(rq2[0]), __float2half_rn(rq2[1])),
        pack2h(__float2half_rn(rq2[2]), __float2half_rn(rq2[3])));
    *(uint2*)&K[d0] = make_uint2(
        pack2h(__float2half_rn(rk1[0]), __float2half_rn(rk1[1])),
        pack2h(__float2half_rn(rk1[2]), __float2half_rn(rk1[3])));
    *(uint2*)&K[d0 + 40] = make_uint2(
        pack2h(__float2half_rn(rk2[0]), __float2half_rn(rk2[1])),
        pack2h(__float2half_rn(rk2[2]), __float2half_rn(rk2[3])));
}

// ---------------------------------------------------------------------------
// V transpose (fp16 -> fp16, pure data movement): g_V16 -> g_Vt [c][h][d][t]
// ---------------------------------------------------------------------------
__global__ __launch_bounds__(256) void vtrans()
{
    __shared__ __half vs[64][88];
    const int tid = threadIdx.x;
    const int t0  = blockIdx.x * 64;
    const int h   = blockIdx.y;
    const int c   = t0 / CHUNK_L;
    const int tloc = t0 - c * CHUNK_L;

    // load 64 rows x 80 halves = 640 uint4
#pragma unroll
    for (int i = 0; i < 3; i++) {
        int idx = tid + i * 256;
        if (idx < 640) {
            int r = idx / 10, j = idx % 10;
            *(uint4*)&vs[r][j * 8] =
                *(const uint4*)&g_V16[(size_t)(t0 + r) * HIDDEN + h * HEAD_DIM + j * 8];
        }
    }
    __syncthreads();

    // write transposed: 80 d x 16 groups of 4 t
#pragma unroll
    for (int i = 0; i < 5; i++) {
        int idx = tid + i * 256;
        int d = idx / 16, t4 = (idx % 16) * 4;
        uint2 w;
        w.x = pack2h(vs[t4 + 0][d], vs[t4 + 1][d]);
        w.y = pack2h(vs[t4 + 2][d], vs[t4 + 3][d]);
        *(uint2*)&g_Vt[((size_t)(c * HEADS + h) * HEAD_DIM + d) * CHUNK_L
                       + tloc + t4] = w;
    }
}

// ---------------------------------------------------------------------------
// Tensor-core flash attention with cp.async double-buffered K/V tiles.
// S k = 80, PV k = 64. One CTA = 128 q-rows x (chunk, head).
// ---------------------------------------------------------------------------
#define LDQ 88    /* 80 + 8 */
#define LDP 72    /* 64 + 8 */
#define KBUF (64 * LDQ * 2)               /* 11264 */
#define VBUF (80 * LDP * 2)               /* 11520 */
#define SM_Q 0
#define SM_K (SM_Q + 128 * LDQ * 2)       /* 22528 */
#define SM_V (SM_K + 2 * KBUF)            /* 45056 */
#define SM_P (SM_V + 2 * VBUF)            /* 68096 */
#define SM_TOT (SM_P + 128 * LDP * 2)     /* 86528 */

__global__ __launch_bounds__(256) void flash_mma()
{
    extern __shared__ char sm[];
    __half (*Q1s)[LDQ] = (__half(*)[LDQ])(sm + SM_Q);
    __half (*P1s)[LDP] = (__half(*)[LDP])(sm + SM_P);

    const int tid  = threadIdx.x;
    const int w    = tid >> 5;
    const int lane = tid & 31;
    const int h    = blockIdx.y;
    const int c    = blockIdx.z;
    const int q0   = c * CHUNK_L + blockIdx.x * 128;
    const uint32_t sb = smem_u32(sm);
    const size_t vBase = (size_t)(c * HEADS + h) * HEAD_DIM * CHUNK_L;

    // load Q tile: 128 x 80 = 1280 uint4 (plain loads; once)
#pragma unroll
    for (int i = 0; i < 5; i++) {
        int idx = tid + i * 256;
        int r = idx / 10, j = idx % 10;
        *(uint4*)&Q1s[r][j * 8] =
            *(const uint4*)&g_Q1[((size_t)(q0 + r) * HEADS + h) * HEAD_DIM + j * 8];
    }

    // per-thread cp.async slots for K (640 uint4) + V (640 uint4)
    uint32_t pd[5];        // smem dst (buf 0)
    const __half* ps[5];   // gmem src (kt 0)
    int pstep[5];          // src element step per kv tile
    int pbs[5];            // smem buf stride
#pragma unroll
    for (int p = 0; p < 5; p++) {
        int idx = tid + p * 256;
        if (idx < 640) {
            int r = idx / 10, j = idx % 10;
            pd[p]    = sb + SM_K + r * (LDQ * 2) + j * 16;
            ps[p]    = g_K1 + ((size_t)(c * CHUNK_L + r) * HEADS + h) * HEAD_DIM + j * 8;
            pstep[p] = 64 * HEADS * HEAD_DIM;
            pbs[p]   = KBUF;
        } else {
            int vx = idx - 640;
            int d = vx >> 3, j = vx & 7;
            pd[p]    = sb + SM_V + d * (LDP * 2) + j * 16;
            ps[p]    = g_Vt + vBase + (size_t)d * CHUNK_L + j * 8;
            pstep[p] = 64;
            pbs[p]   = VBUF;
        }
    }

    const int lrow = lane & 15;
    const int lcol = (lane >> 4) << 3;
    const uint32_t qAddr = smem_u32(&Q1s[w * 16 + lrow][lcol]);
    const uint32_t pAddr = smem_u32(&P1s[w * 16 + lrow][lcol]);
    uint32_t kAddr[4], vAddr[5];
#pragma unroll
    for (int np = 0; np < 4; np++)
        kAddr[np] = sb + SM_K + (np * 16 + lrow) * (LDQ * 2) + lcol * 2;
#pragma unroll
    for (int np = 0; np < 5; np++)
        vAddr[np] = sb + SM_V + (np * 16 + lrow) * (LDP * 2) + lcol * 2;

    const int cr = lane >> 2;
    const int cc = (lane & 3) * 2;
    uint32_t* Prow0 = (uint32_t*)&P1s[w * 16 + cr][0];
    uint32_t* Prow1 = (uint32_t*)&P1s[w * 16 + cr + 8][0];

    float O[10][4];
#pragma unroll
    for (int nt = 0; nt < 10; nt++)
#pragma unroll
        for (int v = 0; v < 4; v++) O[nt][v] = 0.0f;
    float m0 = -1e30f, m1 = -1e30f, l0 = 0.0f, l1 = 0.0f;

    // prefetch kt = 0 into buffer 0
#pragma unroll
    for (int p = 0; p < 5; p++)
        cp16(pd[p], ps[p]);
    cp_commit();

    const int NT = CHUNK_L / 64;
    for (int kt = 0; kt < NT; kt++) {
        const int buf = kt & 1;
        // prefetch kt+1 into other buffer (safe: last iter's PV synced)
        if (kt + 1 < NT) {
#pragma unroll
            for (int p = 0; p < 5; p++)
                cp16(pd[p] + (buf ^ 1) * pbs[p],
                     ps[p] + (size_t)(kt + 1) * pstep[p]);
        }
        cp_commit();
        cp_wait<1>();
        __syncthreads();

        // ---- S = Q @ K^T (k = 80) ----
        const uint32_t kOff = buf * KBUF;
        float s[8][4];
#pragma unroll
        for (int nt = 0; nt < 8; nt++)
#pragma unroll
            for (int v = 0; v < 4; v++) s[nt][v] = 0.0f;
#pragma unroll
        for (int ks = 0; ks < 5; ks++) {
            uint32_t af[4];
            ldsm_x4(af, qAddr + ks * 32);
            uint32_t bf[8][2];
#pragma unroll
            for (int np = 0; np < 4; np++) {
                uint32_t r[4];
                ldsm_x4(r, kAddr[np] + kOff + ks * 32);
                bf[2 * np][0]     = r[0]; bf[2 * np][1]     = r[2];
                bf[2 * np + 1][0] = r[1]; bf[2 * np + 1][1] = r[3];
            }
#pragma unroll
            for (int nt = 0; nt < 8; nt++)
                mma_16816(s[nt], af, bf[nt]);
        }

        // ---- online softmax ----
        float tm0 = -1e30f, tm1 = -1e30f;
#pragma unroll
        for (int nt = 0; nt < 8; nt++) {
            tm0 = fmaxf(tm0, fmaxf(s[nt][0], s[nt][1]));
            tm1 = fmaxf(tm1, fmaxf(s[nt][2], s[nt][3]));
        }
        tm0 = fmaxf(tm0, __shfl_xor_sync(0xffffffffu, tm0, 1));
        tm0 = fmaxf(tm0, __shfl_xor_sync(0xffffffffu, tm0, 2));
        tm1 = fmaxf(tm1, __shfl_xor_sync(0xffffffffu, tm1, 1));
        tm1 = fmaxf(tm1, __shfl_xor_sync(0xffffffffu, tm1, 2));
        const float nm0 = fmaxf(m0, tm0);
        const float nm1 = fmaxf(m1, tm1);
        const float a0 = __expf(m0 - nm0);
        const float a1 = __expf(m1 - nm1);
        m0 = nm0; m1 = nm1;

        float sum0 = 0.0f, sum1 = 0.0f;
#pragma unroll
        for (int nt = 0; nt < 8; nt++) {
            float p00 = __expf(s[nt][0] - nm0);
            float p01 = __expf(s[nt][1] - nm0);
            float p10 = __expf(s[nt][2] - nm1);
            float p11 = __expf(s[nt][3] - nm1);
            sum0 += p00 + p01;
            sum1 += p10 + p11;
            const int cw = (nt * 8 + cc) >> 1;
            Prow0[cw] = pack2h(__float2half_rn(p00), __float2half_rn(p01));
            Prow1[cw] = pack2h(__float2half_rn(p10), __float2half_rn(p11));
        }
        sum0 += __shfl_xor_sync(0xffffffffu, sum0, 1);
        sum0 += __shfl_xor_sync(0xffffffffu, sum0, 2);
        sum1 += __shfl_xor_sync(0xffffffffu, sum1, 1);
        sum1 += __shfl_xor_sync(0xffffffffu, sum1, 2);
        l0 = l0 * a0 + sum0;
        l1 = l1 * a1 + sum1;

#pragma unroll
        for (int nt = 0; nt < 10; nt++) {
            O[nt][0] *= a0; O[nt][1] *= a0;
            O[nt][2] *= a1; O[nt][3] *= a1;
        }
        __syncthreads();

        // ---- O += P @ Vt^T (k = 64, n = 80) ----
        const uint32_t vOff = buf * VBUF;
#pragma unroll
        for (int ks = 0; ks < 4; ks++) {
            uint32_t af[4];
            ldsm_x4(af, pAddr + ks * 32);
            uint32_t bf[10][2];
#pragma unroll
            for (int np = 0; np < 5; np++) {
                uint32_t r[4];
                ldsm_x4(r, vAddr[np] + vOff + ks * 32);
                bf[2 * np][0]     = r[0]; bf[2 * np][1]     = r[2];
                bf[2 * np + 1][0] = r[1]; bf[2 * np + 1][1] = r[3];
            }
#pragma unroll
            for (int nt = 0; nt < 10; nt++)
                mma_16816(O[nt], af, bf[nt]);
        }
        __syncthreads();  // PV done before this buffer is overwritten
    }

    // ---- normalize + single-fp16 output into g_Ap ----
    const float inv0 = 1.0f / l0;
    const float inv1 = 1.0f / l1;
    const int r0 = q0 + w * 16 + cr;
#pragma unroll
    for (int nt = 0; nt < 10; nt++) {
        const int col = h * HEAD_DIM + nt * 8 + cc;
        *(uint32_t*)&g_Ap[(size_t)r0 * HIDDEN + col] =
            pack2h(__float2half_rn(O[nt][0] * inv0),
                   __float2half_rn(O[nt][1] * inv0));
        *(uint32_t*)&g_Ap[(size_t)(r0 + 8) * HIDDEN + col] =
            pack2h(__float2half_rn(O[nt][2] * inv1),
                   __float2half_rn(O[nt][3] * inv1));
    }
}

// ---------------------------------------------------------------------------
extern "C" void kernel_launch(void* const* d_in, const int* in_sizes, int n_in,
                              void* d_out, int out_size)
{
    (void)in_sizes; (void)n_in; (void)out_size;
    const float* x      = (const float*)d_in[0];
    const float* cosp   = (const float*)d_in[1];
    const float* sinp   = (const float*)d_in[2];
    const float* w_qkv  = (const float*)d_in[3];
    const float* b_qkv  = (const float*)d_in[4];
    const float* w_proj = (const float*)d_in[5];
    const float* b_proj = (const float*)d_in[6];
    float* out = (float*)d_out;

    float* qkv = nullptr;
    __half *Aq = nullptr, *Ap = nullptr, *Bq = nullptr, *Bp = nullptr, *V16 = nullptr;
    cudaGetSymbolAddress((void**)&qkv,  g_qkv);
    cudaGetSymbolAddress((void**)&Aq,   g_Aq);
    cudaGetSymbolAddress((void**)&Ap,   g_Ap);
    cudaGetSymbolAddress((void**)&Bq,   g_Bq);
    cudaGetSymbolAddress((void**)&Bp,   g_Bp);
    cudaGetSymbolAddress((void**)&V16,  g_V16);

    cudaFuncSetAttribute(gemm_fp16_mma,
                         cudaFuncAttributeMaxDynamicSharedMemorySize, GSMEM);
    cudaFuncSetAttribute(flash_mma,
                         cudaFuncAttributeMaxDynamicSharedMemorySize, SM_TOT);

    // conversions
    convert_B1<<<dim3(QKVN / 32, HIDDEN / 32), dim3(32, 8)>>>(w_qkv, Bq, HIDDEN, QKVN);
    convert_B1<<<dim3(HIDDEN / 32, HIDDEN / 32), dim3(32, 8)>>>(w_proj, Bp, HIDDEN, HIDDEN);
    {
        int mk = TOTAL * HIDDEN;
        convert_A<<<(mk / 4 + 255) / 256, 256>>>(x, Aq, mk);
    }

    // 1) QKV projection (q,k fp32 -> g_qkv; v fp16 -> g_V16)
    gemm_fp16_mma<<<dim3(QKVN / 128, TOTAL / 128), 128, GSMEM>>>(
        Aq, Bq, b_qkv, qkv, V16, QKVN, HIDDEN);

    // 2) RoPE + V transpose
    {
        int total = TOTAL * HEADS * 10;
        rope_split<<<(total + 255) / 256, 256>>>(cosp, sinp);
    }
    vtrans<<<dim3(TOTAL / 64, HEADS), 256>>>();

    // 3) flash attention (writes fp16 attn into g_Ap)
    flash_mma<<<dim3(CHUNK_L / 128, HEADS, NCHUNK), 256, SM_TOT>>>();

    // 4) output projection (fp16, K = 1280)
    gemm_fp16_mma<<<dim3(HIDDEN / 128, TOTAL / 128), 128, GSMEM>>>(
        Ap, Bp, b_proj, out, nullptr, HIDDEN, HIDDEN);
}

// round 12
// speedup vs baseline: 1.0373x; 1.0373x over previous
#include <cuda_runtime.h>
#include <cuda_fp16.h>
#include <cstdint>

#define TOTAL    8192
#define HIDDEN   1280
#define HEADS    16
#define HEAD_DIM 80
#define NCHUNK   8
#define CHUNK_L  1024
#define QKVN     3840
#define SCALE    0.11180339887498949f  /* 80^-0.5 */

// ---------------- device scratch (no allocs allowed) ----------------
__device__ float  g_qkv [(size_t)TOTAL * QKVN];            // q,k fp32 (v unused)
__device__ __half g_V16 [(size_t)TOTAL * HIDDEN];          // fp16 v (GEMM epilogue)
__device__ __half g_Aq  [(size_t)TOTAL * HIDDEN];          // fp16(x)
__device__ __half g_Ap  [(size_t)TOTAL * HIDDEN];          // fp16(attn)
__device__ __half g_Bq  [(size_t)QKVN  * HIDDEN];          // fp16(w_qkv)^T
__device__ __half g_Bp  [(size_t)HIDDEN* HIDDEN];          // fp16(w_proj)^T
__device__ __half g_Q1 [(size_t)TOTAL * HEADS * HEAD_DIM]; // fp16 roped q
__device__ __half g_K1 [(size_t)TOTAL * HEADS * HEAD_DIM]; // fp16 roped k
__device__ __half g_Vt [(size_t)NCHUNK * HEADS * HEAD_DIM * CHUNK_L];

// ---------------- PTX helpers ----------------
__device__ __forceinline__ uint32_t smem_u32(const void* p) {
    uint32_t a;
    asm("{ .reg .u64 t; cvta.to.shared.u64 t, %1; cvt.u32.u64 %0, t; }"
        : "=r"(a) : "l"(p));
    return a;
}
__device__ __forceinline__ void ldsm_x4(uint32_t* r, uint32_t addr) {
    asm volatile("ldmatrix.sync.aligned.m8n8.x4.shared.b16 {%0,%1,%2,%3}, [%4];"
                 : "=r"(r[0]), "=r"(r[1]), "=r"(r[2]), "=r"(r[3]) : "r"(addr));
}
__device__ __forceinline__ void mma_16816(float* c, const uint32_t* a,
                                          const uint32_t* b) {
    asm volatile(
        "mma.sync.aligned.m16n8k16.row.col.f32.f16.f16.f32 "
        "{%0,%1,%2,%3}, {%4,%5,%6,%7}, {%8,%9}, {%0,%1,%2,%3};"
        : "+f"(c[0]), "+f"(c[1]), "+f"(c[2]), "+f"(c[3])
        : "r"(a[0]), "r"(a[1]), "r"(a[2]), "r"(a[3]), "r"(b[0]), "r"(b[1]));
}
__device__ __forceinline__ void cp16(uint32_t dst, const void* src) {
    asm volatile("cp.async.cg.shared.global [%0], [%1], 16;"
                 :: "r"(dst), "l"(src));
}
__device__ __forceinline__ void cp_commit() {
    asm volatile("cp.async.commit_group;" ::: "memory");
}
template <int W>
__device__ __forceinline__ void cp_wait() {
    asm volatile("cp.async.wait_group %0;" :: "n"(W) : "memory");
}
__device__ __forceinline__ uint32_t pack2h(__half lo, __half hi) {
    return (uint32_t)__half_as_ushort(lo) |
           ((uint32_t)__half_as_ushort(hi) << 16);
}

// ---------------------------------------------------------------------------
// Tensor-core GEMM: C[8192, N] = A * B^T + bias. If Vout != nullptr, columns
// >= 2*HIDDEN are written as fp16 to Vout[t][col-2*HIDDEN] instead of C.
// ---------------------------------------------------------------------------
#define BK     32
#define NST    3
#define LDAE   40
#define ROWB   (LDAE * 2)
#define STAGEB (128 * ROWB)
#define BOFF   (NST * STAGEB)
#define GSMEM  (2 * NST * STAGEB)

__global__ __launch_bounds__(128, 2) void gemm_fp16_mma(
    const __half* __restrict__ A, const __half* __restrict__ B,
    const float* __restrict__ bias, float* __restrict__ C,
    __half* __restrict__ Vout, int N, int K)
{
    extern __shared__ char sm[];
    const int tid  = threadIdx.x;
    const int wid  = tid >> 5;
    const int lane = tid & 31;
    const int m0   = blockIdx.y * 128;
    const int n0   = blockIdx.x * 128;
    const int wm   = wid & 1;
    const int wn   = wid >> 1;

    uint32_t aDst[4], bDst[4];
    const __half *aS[4], *bS[4];
#pragma unroll
    for (int p = 0; p < 4; p++) {
        int u  = tid + p * 128;
        int r  = u >> 2;
        int ch = (u & 3) * 8;
        aDst[p] = smem_u32(sm + r * ROWB + ch * 2);
        bDst[p] = aDst[p] + BOFF;
        aS[p]   = A + (size_t)(m0 + r) * K + ch;
        bS[p]   = B + (size_t)(n0 + r) * K + ch;
    }

    float acc[4][8][4];
#pragma unroll
    for (int mt = 0; mt < 4; mt++)
#pragma unroll
        for (int nt = 0; nt < 8; nt++)
#pragma unroll
            for (int v = 0; v < 4; v++) acc[mt][nt][v] = 0.0f;

    const int lrow  = lane & 15;
    const int lcolb = ((lane >> 4) << 3) * 2;
    uint32_t aAddr[4], bAddr[4];
#pragma unroll
    for (int mt = 0; mt < 4; mt++)
        aAddr[mt] = smem_u32(sm + (wm * 64 + mt * 16 + lrow) * ROWB + lcolb);
#pragma unroll
    for (int np = 0; np < 4; np++)
        bAddr[np] = smem_u32(sm + BOFF + (wn * 64 + np * 16 + lrow) * ROWB + lcolb);

#pragma unroll
    for (int s = 0; s < 2; s++) {
#pragma unroll
        for (int p = 0; p < 4; p++) {
            cp16(aDst[p] + s * STAGEB, aS[p] + s * BK);
            cp16(bDst[p] + s * STAGEB, bS[p] + s * BK);
        }
        cp_commit();
    }

    const int NKB = K / BK;
    for (int kb = 0; kb < NKB; kb++) {
        cp_wait<1>();
        __syncthreads();

        const int nxt = kb + 2;
        if (nxt < NKB) {
            const uint32_t so = (uint32_t)(nxt % NST) * STAGEB;
#pragma unroll
            for (int p = 0; p < 4; p++) {
                cp16(aDst[p] + so, aS[p] + nxt * BK);
                cp16(bDst[p] + so, bS[p] + nxt * BK);
            }
        }
        cp_commit();

        const uint32_t base = (uint32_t)(kb % NST) * STAGEB;
#pragma unroll
        for (int ks = 0; ks < 2; ks++) {
            const uint32_t ko = base + ks * 32;
            uint32_t af[4][4];
#pragma unroll
            for (int mt = 0; mt < 4; mt++)
                ldsm_x4(af[mt], aAddr[mt] + ko);
            uint32_t bf[8][2];
#pragma unroll
            for (int np = 0; np < 4; np++) {
                uint32_t r[4];
                ldsm_x4(r, bAddr[np] + ko);
                bf[2 * np][0]     = r[0]; bf[2 * np][1]     = r[2];
                bf[2 * np + 1][0] = r[1]; bf[2 * np + 1][1] = r[3];
            }
#pragma unroll
            for (int mt = 0; mt < 4; mt++)
#pragma unroll
                for (int nt = 0; nt < 8; nt++)
                    mma_16816(acc[mt][nt], af[mt], bf[nt]);
        }
    }

    const int cr = lane >> 2;
    const int cc = (lane & 3) * 2;
#pragma unroll
    for (int mt = 0; mt < 4; mt++) {
        const int r0 = m0 + wm * 64 + mt * 16 + cr;
#pragma unroll
        for (int nt = 0; nt < 8; nt++) {
            const int col = n0 + wn * 64 + nt * 8 + cc;
            const float b0 = __ldg(&bias[col]);
            const float b1 = __ldg(&bias[col + 1]);
            float o00 = acc[mt][nt][0] + b0, o01 = acc[mt][nt][1] + b1;
            float o10 = acc[mt][nt][2] + b0, o11 = acc[mt][nt][3] + b1;
            if (Vout != nullptr && col >= 2 * HIDDEN) {
                const int vc = col - 2 * HIDDEN;
                *(uint32_t*)&Vout[(size_t)r0 * HIDDEN + vc] =
                    pack2h(__float2half_rn(o00), __float2half_rn(o01));
                *(uint32_t*)&Vout[(size_t)(r0 + 8) * HIDDEN + vc] =
                    pack2h(__float2half_rn(o10), __float2half_rn(o11));
            } else {
                float2 v0, v1;
                v0.x = o00; v0.y = o01;
                v1.x = o10; v1.y = o11;
                *(float2*)&C[(size_t)r0 * N + col]       = v0;
                *(float2*)&C[(size_t)(r0 + 8) * N + col] = v1;
            }
        }
    }
}

// ---------------------------------------------------------------------------
// Plain fp16 conversion of activations: X[MK] fp32 -> O[MK] fp16
// ---------------------------------------------------------------------------
__global__ __launch_bounds__(256) void convert_A(
    const float* __restrict__ X, __half* __restrict__ O, int MK)
{
    int idx = (blockIdx.x * 256 + threadIdx.x) * 4;
    if (idx >= MK) return;
    float4 v = *(const float4*)&X[idx];
    uint32_t p0 = pack2h(__float2half_rn(v.x), __float2half_rn(v.y));
    uint32_t p1 = pack2h(__float2half_rn(v.z), __float2half_rn(v.w));
    *(uint2*)&O[idx] = make_uint2(p0, p1);
}

// ---------------------------------------------------------------------------
// fp16 weight transpose: W[K,N] fp32 -> O[N,K]
// ---------------------------------------------------------------------------
__global__ __launch_bounds__(256) void convert_B1(
    const float* __restrict__ W, __half* __restrict__ O, int K, int N)
{
    __shared__ float t[32][33];
    const int k0 = blockIdx.y * 32, n0 = blockIdx.x * 32;
    const int tx = threadIdx.x, ty = threadIdx.y;
#pragma unroll
    for (int i = 0; i < 32; i += 8)
        t[ty + i][tx] = W[(size_t)(k0 + ty + i) * N + n0 + tx];
    __syncthreads();
#pragma unroll
    for (int i = 0; i < 32; i += 8) {
        int n = n0 + ty + i, k = k0 + tx;
        O[(size_t)n * K + k] = __float2half_rn(t[tx][ty + i]);
    }
}

// ---------------------------------------------------------------------------
// RoPE + fp16 conversion of q,k, vectorized x4 (q pre-scaled by hd^-0.5).
// ---------------------------------------------------------------------------
__global__ __launch_bounds__(256) void rope_split(
    const float* __restrict__ cosp, const float* __restrict__ sinp)
{
    int idx = blockIdx.x * blockDim.x + threadIdx.x;
    const int total = TOTAL * HEADS * 10;
    if (idx >= total) return;
    int b = idx % 10;
    int h = (idx / 10) % HEADS;
    int t = idx / (10 * HEADS);
    int d0 = b * 4;

    const float* row = g_qkv + (size_t)t * QKVN;
    int qi = h * HEAD_DIM + d0;

    float4 q1 = *(const float4*)&row[qi];
    float4 q2 = *(const float4*)&row[qi + 40];
    float4 k1 = *(const float4*)&row[HIDDEN + qi];
    float4 k2 = *(const float4*)&row[HIDDEN + qi + 40];
    float4 c1 = *(const float4*)&cosp[t * HEAD_DIM + d0];
    float4 s1 = *(const float4*)&sinp[t * HEAD_DIM + d0];
    float4 c2 = *(const float4*)&cosp[t * HEAD_DIM + d0 + 40];
    float4 s2 = *(const float4*)&sinp[t * HEAD_DIM + d0 + 40];

    float rq1[4], rq2[4], rk1[4], rk2[4];
    const float* q1a = &q1.x; const float* q2a = &q2.x;
    const float* k1a = &k1.x; const float* k2a = &k2.x;
    const float* c1a = &c1.x; const float* s1a = &s1.x;
    const float* c2a = &c2.x; const float* s2a = &s2.x;
#pragma unroll
    for (int i = 0; i < 4; i++) {
        rq1[i] = (q1a[i] * c1a[i] - q2a[i] * s1a[i]) * SCALE;
        rq2[i] = (q2a[i] * c2a[i] + q1a[i] * s2a[i]) * SCALE;
        rk1[i] = k1a[i] * c1a[i] - k2a[i] * s1a[i];
        rk2[i] = k2a[i] * c2a[i] + k1a[i] * s2a[i];
    }

    __half* Q = g_Q1 + ((size_t)t * HEADS + h) * HEAD_DIM;
    __half* K = g_K1 + ((size_t)t * HEADS + h) * HEAD_DIM;
    *(uint2*)&Q[d0] = make_uint2(
        pack2h(__float2half_rn(rq1[0]), __float2half_rn(rq1[1])),
        pack2h(__float2half_rn(rq1[2]), __float2half_rn(rq1[3])));
    *(uint2*)&Q[d0 + 40] = make_uint2(
        pack2h(__float2half_rn(rq2[0]), __float2half_rn(rq2[1])),
        pack2h(__float2half_rn(rq2[2]), __float2half_rn(rq2[3])));
    *(uint2*)&K[d0] = make_uint2(
        pack2h(__float2half_rn(rk1[0]), __float2half_rn(rk1[1])),
        pack2h(__float2half_rn(rk1[2]), __float2half_rn(rk1[3])));
    *(uint2*)&K[d0 + 40] = make_uint2(
        pack2h(__float2half_rn(rk2[0]), __float2half_rn(rk2[1])),
        pack2h(__float2half_rn(rk2[2]), __float2half_rn(rk2[3])));
}

// ---------------------------------------------------------------------------
// V transpose (fp16 -> fp16, pure data movement): g_V16 -> g_Vt [c][h][d][t]
// ---------------------------------------------------------------------------
__global__ __launch_bounds__(256) void vtrans()
{
    __shared__ __half vs[64][88];
    const int tid = threadIdx.x;
    const int t0  = blockIdx.x * 64;
    const int h   = blockIdx.y;
    const int c   = t0 / CHUNK_L;
    const int tloc = t0 - c * CHUNK_L;

#pragma unroll
    for (int i = 0; i < 3; i++) {
        int idx = tid + i * 256;
        if (idx < 640) {
            int r = idx / 10, j = idx % 10;
            *(uint4*)&vs[r][j * 8] =
                *(const uint4*)&g_V16[(size_t)(t0 + r) * HIDDEN + h * HEAD_DIM + j * 8];
        }
    }
    __syncthreads();

#pragma unroll
    for (int i = 0; i < 5; i++) {
        int idx = tid + i * 256;
        int d = idx / 16, t4 = (idx % 16) * 4;
        uint2 w;
        w.x = pack2h(vs[t4 + 0][d], vs[t4 + 1][d]);
        w.y = pack2h(vs[t4 + 2][d], vs[t4 + 3][d]);
        *(uint2*)&g_Vt[((size_t)(c * HEADS + h) * HEAD_DIM + d) * CHUNK_L
                       + tloc + t4] = w;
    }
}

// ---------------------------------------------------------------------------
// Tensor-core flash attention — R10 version (single-buffer, 63.7KB smem,
// 3 CTAs/SM). S k = 80, PV k = 64. One CTA = 128 q-rows x (chunk, head).
// ---------------------------------------------------------------------------
#define LDQ 88    /* 80 + 8 */
#define LDP 72    /* 64 + 8 */
#define SM_Q 0
#define SM_K (SM_Q + 128 * LDQ * 2)       /* 22528 */
#define SM_V (SM_K + 64 * LDQ * 2)        /* 33792 */
#define SM_P (SM_V + 80 * LDP * 2)        /* 45312 */
#define SM_TOT (SM_P + 128 * LDP * 2)     /* 63744 */

__global__ __launch_bounds__(256) void flash_mma()
{
    extern __shared__ char sm[];
    __half (*Q1s)[LDQ] = (__half(*)[LDQ])(sm + SM_Q);
    __half (*K1s)[LDQ] = (__half(*)[LDQ])(sm + SM_K);
    __half (*Vts)[LDP] = (__half(*)[LDP])(sm + SM_V);
    __half (*P1s)[LDP] = (__half(*)[LDP])(sm + SM_P);

    const int tid  = threadIdx.x;
    const int w    = tid >> 5;
    const int lane = tid & 31;
    const int h    = blockIdx.y;
    const int c    = blockIdx.z;
    const int q0   = c * CHUNK_L + blockIdx.x * 128;

    // load Q tile: 128 x 80 = 1280 uint4
#pragma unroll
    for (int i = 0; i < 5; i++) {
        int idx = tid + i * 256;
        int r = idx / 10, j = idx % 10;
        *(uint4*)&Q1s[r][j * 8] =
            *(const uint4*)&g_Q1[((size_t)(q0 + r) * HEADS + h) * HEAD_DIM + j * 8];
    }

    const int lrow = lane & 15;
    const int lcol = (lane >> 4) << 3;
    const uint32_t qAddr = smem_u32(&Q1s[w * 16 + lrow][lcol]);
    const uint32_t pAddr = smem_u32(&P1s[w * 16 + lrow][lcol]);
    uint32_t kAddr[4], vAddr[5];
#pragma unroll
    for (int np = 0; np < 4; np++)
        kAddr[np] = smem_u32(&K1s[np * 16 + lrow][lcol]);
#pragma unroll
    for (int np = 0; np < 5; np++)
        vAddr[np] = smem_u32(&Vts[np * 16 + lrow][lcol]);

    const int cr = lane >> 2;
    const int cc = (lane & 3) * 2;
    uint32_t* Prow0 = (uint32_t*)&P1s[w * 16 + cr][0];
    uint32_t* Prow1 = (uint32_t*)&P1s[w * 16 + cr + 8][0];

    float O[10][4];
#pragma unroll
    for (int nt = 0; nt < 10; nt++)
#pragma unroll
        for (int v = 0; v < 4; v++) O[nt][v] = 0.0f;
    float m0 = -1e30f, m1 = -1e30f, l0 = 0.0f, l1 = 0.0f;

    const size_t vBase = (size_t)(c * HEADS + h) * HEAD_DIM * CHUNK_L;

    for (int kt = 0; kt < CHUNK_L / 64; kt++) {
        const int kv0 = kt * 64;
        __syncthreads();
        // load K tile (640 uint4) + Vt tile (640 uint4)
#pragma unroll
        for (int i = 0; i < 5; i++) {
            int idx = tid + i * 256;
            if (idx < 640) {
                int r = idx / 10, j = idx % 10;
                *(uint4*)&K1s[r][j * 8] =
                    *(const uint4*)&g_K1[((size_t)(c * CHUNK_L + kv0 + r) * HEADS + h) * HEAD_DIM + j * 8];
            } else {
                int vx = idx - 640;
                int d = vx >> 3, j = vx & 7;
                *(uint4*)&Vts[d][j * 8] =
                    *(const uint4*)&g_Vt[vBase + (size_t)d * CHUNK_L + kv0 + j * 8];
            }
        }
        __syncthreads();

        // ---- S = Q @ K^T (k = 80) ----
        float s[8][4];
#pragma unroll
        for (int nt = 0; nt < 8; nt++)
#pragma unroll
            for (int v = 0; v < 4; v++) s[nt][v] = 0.0f;
#pragma unroll
        for (int ks = 0; ks < 5; ks++) {
            uint32_t af[4];
            ldsm_x4(af, qAddr + ks * 32);
            uint32_t bf[8][2];
#pragma unroll
            for (int np = 0; np < 4; np++) {
                uint32_t r[4];
                ldsm_x4(r, kAddr[np] + ks * 32);
                bf[2 * np][0]     = r[0]; bf[2 * np][1]     = r[2];
                bf[2 * np + 1][0] = r[1]; bf[2 * np + 1][1] = r[3];
            }
#pragma unroll
            for (int nt = 0; nt < 8; nt++)
                mma_16816(s[nt], af, bf[nt]);
        }

        // ---- online softmax ----
        float tm0 = -1e30f, tm1 = -1e30f;
#pragma unroll
        for (int nt = 0; nt < 8; nt++) {
            tm0 = fmaxf(tm0, fmaxf(s[nt][0], s[nt][1]));
            tm1 = fmaxf(tm1, fmaxf(s[nt][2], s[nt][3]));
        }
        tm0 = fmaxf(tm0, __shfl_xor_sync(0xffffffffu, tm0, 1));
        tm0 = fmaxf(tm0, __shfl_xor_sync(0xffffffffu, tm0, 2));
        tm1 = fmaxf(tm1, __shfl_xor_sync(0xffffffffu, tm1, 1));
        tm1 = fmaxf(tm1, __shfl_xor_sync(0xffffffffu, tm1, 2));
        const float nm0 = fmaxf(m0, tm0);
        const float nm1 = fmaxf(m1, tm1);
        const float a0 = __expf(m0 - nm0);
        const float a1 = __expf(m1 - nm1);
        m0 = nm0; m1 = nm1;

        float sum0 = 0.0f, sum1 = 0.0f;
#pragma unroll
        for (int nt = 0; nt < 8; nt++) {
            float p00 = __expf(s[nt][0] - nm0);
            float p01 = __expf(s[nt][1] - nm0);
            float p10 = __expf(s[nt][2] - nm1);
            float p11 = __expf(s[nt][3] - nm1);
            sum0 += p00 + p01;
            sum1 += p10 + p11;
            const int cw = (nt * 8 + cc) >> 1;
            Prow0[cw] = pack2h(__float2half_rn(p00), __float2half_rn(p01));
            Prow1[cw] = pack2h(__float2half_rn(p10), __float2half_rn(p11));
        }
        sum0 += __shfl_xor_sync(0xffffffffu, sum0, 1);
        sum0 += __shfl_xor_sync(0xffffffffu, sum0, 2);
        sum1 += __shfl_xor_sync(0xffffffffu, sum1, 1);
        sum1 += __shfl_xor_sync(0xffffffffu, sum1, 2);
        l0 = l0 * a0 + sum0;
        l1 = l1 * a1 + sum1;

#pragma unroll
        for (int nt = 0; nt < 10; nt++) {
            O[nt][0] *= a0; O[nt][1] *= a0;
            O[nt][2] *= a1; O[nt][3] *= a1;
        }
        __syncthreads();

        // ---- O += P @ Vt^T (k = 64, n = 80) ----
#pragma unroll
        for (int ks = 0; ks < 4; ks++) {
            uint32_t af[4];
            ldsm_x4(af, pAddr + ks * 32);
            uint32_t bf[10][2];
#pragma unroll
            for (int np = 0; np < 5; np++) {
                uint32_t r[4];
                ldsm_x4(r, vAddr[np] + ks * 32);
                bf[2 * np][0]     = r[0]; bf[2 * np][1]     = r[2];
                bf[2 * np + 1][0] = r[1]; bf[2 * np + 1][1] = r[3];
            }
#pragma unroll
            for (int nt = 0; nt < 10; nt++)
                mma_16816(O[nt], af, bf[nt]);
        }
    }

    // ---- normalize + single-fp16 output into g_Ap ----
    const float inv0 = 1.0f / l0;
    const float inv1 = 1.0f / l1;
    const int r0 = q0 + w * 16 + cr;
#pragma unroll
    for (int nt = 0; nt < 10; nt++) {
        const int col = h * HEAD_DIM + nt * 8 + cc;
        *(uint32_t*)&g_Ap[(size_t)r0 * HIDDEN + col] =
            pack2h(__float2half_rn(O[nt][0] * inv0),
                   __float2half_rn(O[nt][1] * inv0));
        *(uint32_t*)&g_Ap[(size_t)(r0 + 8) * HIDDEN + col] =
            pack2h(__float2half_rn(O[nt][2] * inv1),
                   __float2half_rn(O[nt][3] * inv1));
    }
}

// ---------------------------------------------------------------------------
extern "C" void kernel_launch(void* const* d_in, const int* in_sizes, int n_in,
                              void* d_out, int out_size)
{
    (void)in_sizes; (void)n_in; (void)out_size;
    const float* x      = (const float*)d_in[0];
    const float* cosp   = (const float*)d_in[1];
    const float* sinp   = (const float*)d_in[2];
    const float* w_qkv  = (const float*)d_in[3];
    const float* b_qkv  = (const float*)d_in[4];
    const float* w_proj = (const float*)d_in[5];
    const float* b_proj = (const float*)d_in[6];
    float* out = (float*)d_out;

    float* qkv = nullptr;
    __half *Aq = nullptr, *Ap = nullptr, *Bq = nullptr, *Bp = nullptr, *V16 = nullptr;
    cudaGetSymbolAddress((void**)&qkv,  g_qkv);
    cudaGetSymbolAddress((void**)&Aq,   g_Aq);
    cudaGetSymbolAddress((void**)&Ap,   g_Ap);
    cudaGetSymbolAddress((void**)&Bq,   g_Bq);
    cudaGetSymbolAddress((void**)&Bp,   g_Bp);
    cudaGetSymbolAddress((void**)&V16,  g_V16);

    cudaFuncSetAttribute(gemm_fp16_mma,
                         cudaFuncAttributeMaxDynamicSharedMemorySize, GSMEM);
    cudaFuncSetAttribute(flash_mma,
                         cudaFuncAttributeMaxDynamicSharedMemorySize, SM_TOT);

    // conversions
    convert_B1<<<dim3(QKVN / 32, HIDDEN / 32), dim3(32, 8)>>>(w_qkv, Bq, HIDDEN, QKVN);
    convert_B1<<<dim3(HIDDEN / 32, HIDDEN / 32), dim3(32, 8)>>>(w_proj, Bp, HIDDEN, HIDDEN);
    {
        int mk = TOTAL * HIDDEN;
        convert_A<<<(mk / 4 + 255) / 256, 256>>>(x, Aq, mk);
    }

    // 1) QKV projection (q,k fp32 -> g_qkv; v fp16 -> g_V16)
    gemm_fp16_mma<<<dim3(QKVN / 128, TOTAL / 128), 128, GSMEM>>>(
        Aq, Bq, b_qkv, qkv, V16, QKVN, HIDDEN);

    // 2) RoPE + V transpose
    {
        int total = TOTAL * HEADS * 10;
        rope_split<<<(total + 255) / 256, 256>>>(cosp, sinp);
    }
    vtrans<<<dim3(TOTAL / 64, HEADS), 256>>>();

    // 3) flash attention (writes fp16 attn into g_Ap)
    flash_mma<<<dim3(CHUNK_L / 128, HEADS, NCHUNK), 256, SM_TOT>>>();

    // 4) output projection (fp16, K = 1280)
    gemm_fp16_mma<<<dim3(HIDDEN / 128, TOTAL / 128), 128, GSMEM>>>(
        Ap, Bp, b_proj, out, nullptr, HIDDEN, HIDDEN);
}

// round 13
// speedup vs baseline: 1.0507x; 1.0129x over previous
#include <cuda_runtime.h>
#include <cuda_fp16.h>
#include <cstdint>

#define TOTAL    8192
#define HIDDEN   1280
#define HEADS    16
#define HEAD_DIM 80
#define NCHUNK   8
#define CHUNK_L  1024
#define QKVN     3840
#define SCALE    0.11180339887498949f  /* 80^-0.5 */

// ---------------- device scratch (no allocs allowed) ----------------
__device__ __half g_QK16[(size_t)TOTAL * 2 * HIDDEN];      // fp16 q|k (GEMM epi)
__device__ __half g_V16 [(size_t)TOTAL * HIDDEN];          // fp16 v  (GEMM epi)
__device__ __half g_Aq  [(size_t)TOTAL * HIDDEN];          // fp16(x)
__device__ __half g_Ap  [(size_t)TOTAL * HIDDEN];          // fp16(attn)
__device__ __half g_Bq  [(size_t)QKVN  * HIDDEN];          // fp16(w_qkv)^T
__device__ __half g_Bp  [(size_t)HIDDEN* HIDDEN];          // fp16(w_proj)^T
__device__ __half g_Q1 [(size_t)TOTAL * HEADS * HEAD_DIM]; // fp16 roped q
__device__ __half g_K1 [(size_t)TOTAL * HEADS * HEAD_DIM]; // fp16 roped k
__device__ __half g_Vt [(size_t)NCHUNK * HEADS * HEAD_DIM * CHUNK_L];

// ---------------- PTX helpers ----------------
__device__ __forceinline__ uint32_t smem_u32(const void* p) {
    uint32_t a;
    asm("{ .reg .u64 t; cvta.to.shared.u64 t, %1; cvt.u32.u64 %0, t; }"
        : "=r"(a) : "l"(p));
    return a;
}
__device__ __forceinline__ void ldsm_x4(uint32_t* r, uint32_t addr) {
    asm volatile("ldmatrix.sync.aligned.m8n8.x4.shared.b16 {%0,%1,%2,%3}, [%4];"
                 : "=r"(r[0]), "=r"(r[1]), "=r"(r[2]), "=r"(r[3]) : "r"(addr));
}
__device__ __forceinline__ void mma_16816(float* c, const uint32_t* a,
                                          const uint32_t* b) {
    asm volatile(
        "mma.sync.aligned.m16n8k16.row.col.f32.f16.f16.f32 "
        "{%0,%1,%2,%3}, {%4,%5,%6,%7}, {%8,%9}, {%0,%1,%2,%3};"
        : "+f"(c[0]), "+f"(c[1]), "+f"(c[2]), "+f"(c[3])
        : "r"(a[0]), "r"(a[1]), "r"(a[2]), "r"(a[3]), "r"(b[0]), "r"(b[1]));
}
__device__ __forceinline__ void cp16(uint32_t dst, const void* src) {
    asm volatile("cp.async.cg.shared.global [%0], [%1], 16;"
                 :: "r"(dst), "l"(src));
}
__device__ __forceinline__ void cp_commit() {
    asm volatile("cp.async.commit_group;" ::: "memory");
}
template <int W>
__device__ __forceinline__ void cp_wait() {
    asm volatile("cp.async.wait_group %0;" :: "n"(W) : "memory");
}
__device__ __forceinline__ uint32_t pack2h(__half lo, __half hi) {
    return (uint32_t)__half_as_ushort(lo) |
           ((uint32_t)__half_as_ushort(hi) << 16);
}
union U2H4 { uint2 u; __half h[4]; };

// ---------------------------------------------------------------------------
// Tensor-core GEMM: out = A * B^T + bias.
// QKV mode (QK16 != null): all outputs fp16 — cols < 2*HIDDEN to QK16,
// cols >= 2*HIDDEN to V16. Proj mode: fp32 to C.
// ---------------------------------------------------------------------------
#define BK     32
#define NST    3
#define LDAE   40
#define ROWB   (LDAE * 2)
#define STAGEB (128 * ROWB)
#define BOFF   (NST * STAGEB)
#define GSMEM  (2 * NST * STAGEB)

__global__ __launch_bounds__(128, 2) void gemm_fp16_mma(
    const __half* __restrict__ A, const __half* __restrict__ B,
    const float* __restrict__ bias, float* __restrict__ C,
    __half* __restrict__ QK16, __half* __restrict__ V16, int N, int K)
{
    extern __shared__ char sm[];
    const int tid  = threadIdx.x;
    const int wid  = tid >> 5;
    const int lane = tid & 31;
    const int m0   = blockIdx.y * 128;
    const int n0   = blockIdx.x * 128;
    const int wm   = wid & 1;
    const int wn   = wid >> 1;

    uint32_t aDst[4], bDst[4];
    const __half *aS[4], *bS[4];
#pragma unroll
    for (int p = 0; p < 4; p++) {
        int u  = tid + p * 128;
        int r  = u >> 2;
        int ch = (u & 3) * 8;
        aDst[p] = smem_u32(sm + r * ROWB + ch * 2);
        bDst[p] = aDst[p] + BOFF;
        aS[p]   = A + (size_t)(m0 + r) * K + ch;
        bS[p]   = B + (size_t)(n0 + r) * K + ch;
    }

    float acc[4][8][4];
#pragma unroll
    for (int mt = 0; mt < 4; mt++)
#pragma unroll
        for (int nt = 0; nt < 8; nt++)
#pragma unroll
            for (int v = 0; v < 4; v++) acc[mt][nt][v] = 0.0f;

    const int lrow  = lane & 15;
    const int lcolb = ((lane >> 4) << 3) * 2;
    uint32_t aAddr[4], bAddr[4];
#pragma unroll
    for (int mt = 0; mt < 4; mt++)
        aAddr[mt] = smem_u32(sm + (wm * 64 + mt * 16 + lrow) * ROWB + lcolb);
#pragma unroll
    for (int np = 0; np < 4; np++)
        bAddr[np] = smem_u32(sm + BOFF + (wn * 64 + np * 16 + lrow) * ROWB + lcolb);

#pragma unroll
    for (int s = 0; s < 2; s++) {
#pragma unroll
        for (int p = 0; p < 4; p++) {
            cp16(aDst[p] + s * STAGEB, aS[p] + s * BK);
            cp16(bDst[p] + s * STAGEB, bS[p] + s * BK);
        }
        cp_commit();
    }

    const int NKB = K / BK;
    for (int kb = 0; kb < NKB; kb++) {
        cp_wait<1>();
        __syncthreads();

        const int nxt = kb + 2;
        if (nxt < NKB) {
            const uint32_t so = (uint32_t)(nxt % NST) * STAGEB;
#pragma unroll
            for (int p = 0; p < 4; p++) {
                cp16(aDst[p] + so, aS[p] + nxt * BK);
                cp16(bDst[p] + so, bS[p] + nxt * BK);
            }
        }
        cp_commit();

        const uint32_t base = (uint32_t)(kb % NST) * STAGEB;
#pragma unroll
        for (int ks = 0; ks < 2; ks++) {
            const uint32_t ko = base + ks * 32;
            uint32_t af[4][4];
#pragma unroll
            for (int mt = 0; mt < 4; mt++)
                ldsm_x4(af[mt], aAddr[mt] + ko);
            uint32_t bf[8][2];
#pragma unroll
            for (int np = 0; np < 4; np++) {
                uint32_t r[4];
                ldsm_x4(r, bAddr[np] + ko);
                bf[2 * np][0]     = r[0]; bf[2 * np][1]     = r[2];
                bf[2 * np + 1][0] = r[1]; bf[2 * np + 1][1] = r[3];
            }
#pragma unroll
            for (int mt = 0; mt < 4; mt++)
#pragma unroll
                for (int nt = 0; nt < 8; nt++)
                    mma_16816(acc[mt][nt], af[mt], bf[nt]);
        }
    }

    const int cr = lane >> 2;
    const int cc = (lane & 3) * 2;
#pragma unroll
    for (int mt = 0; mt < 4; mt++) {
        const int r0 = m0 + wm * 64 + mt * 16 + cr;
#pragma unroll
        for (int nt = 0; nt < 8; nt++) {
            const int col = n0 + wn * 64 + nt * 8 + cc;
            const float b0 = __ldg(&bias[col]);
            const float b1 = __ldg(&bias[col + 1]);
            float o00 = acc[mt][nt][0] + b0, o01 = acc[mt][nt][1] + b1;
            float o10 = acc[mt][nt][2] + b0, o11 = acc[mt][nt][3] + b1;
            if (QK16 != nullptr) {
                uint32_t w0 = pack2h(__float2half_rn(o00), __float2half_rn(o01));
                uint32_t w1 = pack2h(__float2half_rn(o10), __float2half_rn(o11));
                if (col < 2 * HIDDEN) {
                    *(uint32_t*)&QK16[(size_t)r0 * (2 * HIDDEN) + col] = w0;
                    *(uint32_t*)&QK16[(size_t)(r0 + 8) * (2 * HIDDEN) + col] = w1;
                } else {
                    const int vc = col - 2 * HIDDEN;
                    *(uint32_t*)&V16[(size_t)r0 * HIDDEN + vc] = w0;
                    *(uint32_t*)&V16[(size_t)(r0 + 8) * HIDDEN + vc] = w1;
                }
            } else {
                float2 v0, v1;
                v0.x = o00; v0.y = o01;
                v1.x = o10; v1.y = o11;
                *(float2*)&C[(size_t)r0 * N + col]       = v0;
                *(float2*)&C[(size_t)(r0 + 8) * N + col] = v1;
            }
        }
    }
}

// ---------------------------------------------------------------------------
// Plain fp16 conversion of activations: X[MK] fp32 -> O[MK] fp16
// ---------------------------------------------------------------------------
__global__ __launch_bounds__(256) void convert_A(
    const float* __restrict__ X, __half* __restrict__ O, int MK)
{
    int idx = (blockIdx.x * 256 + threadIdx.x) * 4;
    if (idx >= MK) return;
    float4 v = *(const float4*)&X[idx];
    uint32_t p0 = pack2h(__float2half_rn(v.x), __float2half_rn(v.y));
    uint32_t p1 = pack2h(__float2half_rn(v.z), __float2half_rn(v.w));
    *(uint2*)&O[idx] = make_uint2(p0, p1);
}

// ---------------------------------------------------------------------------
// Both weight transposes in one launch. z=0: w_qkv (N=QKVN), z=1: w_proj.
// ---------------------------------------------------------------------------
__global__ __launch_bounds__(256) void convert_Bb(
    const float* __restrict__ Wq, const float* __restrict__ Wp,
    __half* __restrict__ Oq, __half* __restrict__ Op)
{
    const float* W; __half* O; int N;
    if (blockIdx.z == 0) { W = Wq; O = Oq; N = QKVN; }
    else {
        if (blockIdx.x >= HIDDEN / 32) return;
        W = Wp; O = Op; N = HIDDEN;
    }
    const int K = HIDDEN;

    __shared__ float t[32][33];
    const int k0 = blockIdx.y * 32, n0 = blockIdx.x * 32;
    const int tx = threadIdx.x, ty = threadIdx.y;
#pragma unroll
    for (int i = 0; i < 32; i += 8)
        t[ty + i][tx] = W[(size_t)(k0 + ty + i) * N + n0 + tx];
    __syncthreads();
#pragma unroll
    for (int i = 0; i < 32; i += 8) {
        int n = n0 + ty + i, k = k0 + tx;
        O[(size_t)n * K + k] = __float2half_rn(t[tx][ty + i]);
    }
}

// ---------------------------------------------------------------------------
// Fused RoPE (fp16 in/out, vectorized x4) + V transpose, one launch.
// Blocks [0, RS_BLOCKS): rope. Blocks [RS_BLOCKS, +VT_BLOCKS): vtrans.
// ---------------------------------------------------------------------------
#define RS_BLOCKS (TOTAL * HEADS * 10 / 256)         /* 5120 */
#define VT_BLOCKS ((TOTAL / 64) * HEADS)             /* 2048 */

__global__ __launch_bounds__(256) void rope_vtrans(
    const float* __restrict__ cosp, const float* __restrict__ sinp)
{
    __shared__ __half vs[64][88];
    const int tid = threadIdx.x;

    if (blockIdx.x < RS_BLOCKS) {
        // ---- RoPE path ----
        int idx = blockIdx.x * 256 + tid;
        int b = idx % 10;
        int h = (idx / 10) % HEADS;
        int t = idx / (10 * HEADS);
        int d0 = b * 4;

        const __half* row = g_QK16 + (size_t)t * (2 * HIDDEN);
        int qi = h * HEAD_DIM + d0;

        U2H4 q1, q2, k1, k2;
        q1.u = *(const uint2*)&row[qi];
        q2.u = *(const uint2*)&row[qi + 40];
        k1.u = *(const uint2*)&row[HIDDEN + qi];
        k2.u = *(const uint2*)&row[HIDDEN + qi + 40];
        float4 c1 = *(const float4*)&cosp[t * HEAD_DIM + d0];
        float4 s1 = *(const float4*)&sinp[t * HEAD_DIM + d0];
        float4 c2 = *(const float4*)&cosp[t * HEAD_DIM + d0 + 40];
        float4 s2 = *(const float4*)&sinp[t * HEAD_DIM + d0 + 40];

        const float* c1a = &c1.x; const float* s1a = &s1.x;
        const float* c2a = &c2.x; const float* s2a = &s2.x;
        float rq1[4], rq2[4], rk1[4], rk2[4];
#pragma unroll
        for (int i = 0; i < 4; i++) {
            float q1f = __half2float(q1.h[i]), q2f = __half2float(q2.h[i]);
            float k1f = __half2float(k1.h[i]), k2f = __half2float(k2.h[i]);
            rq1[i] = (q1f * c1a[i] - q2f * s1a[i]) * SCALE;
            rq2[i] = (q2f * c2a[i] + q1f * s2a[i]) * SCALE;
            rk1[i] = k1f * c1a[i] - k2f * s1a[i];
            rk2[i] = k2f * c2a[i] + k1f * s2a[i];
        }

        __half* Q = g_Q1 + ((size_t)t * HEADS + h) * HEAD_DIM;
        __half* K = g_K1 + ((size_t)t * HEADS + h) * HEAD_DIM;
        *(uint2*)&Q[d0] = make_uint2(
            pack2h(__float2half_rn(rq1[0]), __float2half_rn(rq1[1])),
            pack2h(__float2half_rn(rq1[2]), __float2half_rn(rq1[3])));
        *(uint2*)&Q[d0 + 40] = make_uint2(
            pack2h(__float2half_rn(rq2[0]), __float2half_rn(rq2[1])),
            pack2h(__float2half_rn(rq2[2]), __float2half_rn(rq2[3])));
        *(uint2*)&K[d0] = make_uint2(
            pack2h(__float2half_rn(rk1[0]), __float2half_rn(rk1[1])),
            pack2h(__float2half_rn(rk1[2]), __float2half_rn(rk1[3])));
        *(uint2*)&K[d0 + 40] = make_uint2(
            pack2h(__float2half_rn(rk2[0]), __float2half_rn(rk2[1])),
            pack2h(__float2half_rn(rk2[2]), __float2half_rn(rk2[3])));
    } else {
        // ---- V transpose path ----
        const int vb = blockIdx.x - RS_BLOCKS;
        const int t0 = (vb % (TOTAL / 64)) * 64;
        const int h  = vb / (TOTAL / 64);
        const int c  = t0 / CHUNK_L;
        const int tloc = t0 - c * CHUNK_L;

#pragma unroll
        for (int i = 0; i < 3; i++) {
            int idx = tid + i * 256;
            if (idx < 640) {
                int r = idx / 10, j = idx % 10;
                *(uint4*)&vs[r][j * 8] =
                    *(const uint4*)&g_V16[(size_t)(t0 + r) * HIDDEN + h * HEAD_DIM + j * 8];
            }
        }
        __syncthreads();

#pragma unroll
        for (int i = 0; i < 5; i++) {
            int idx = tid + i * 256;
            int d = idx / 16, t4 = (idx % 16) * 4;
            uint2 w;
            w.x = pack2h(vs[t4 + 0][d], vs[t4 + 1][d]);
            w.y = pack2h(vs[t4 + 2][d], vs[t4 + 3][d]);
            *(uint2*)&g_Vt[((size_t)(c * HEADS + h) * HEAD_DIM + d) * CHUNK_L
                           + tloc + t4] = w;
        }
    }
}

// ---------------------------------------------------------------------------
// Tensor-core flash attention — verified R10/R12 version (63.7KB, 3 CTA/SM).
// ---------------------------------------------------------------------------
#define LDQ 88    /* 80 + 8 */
#define LDP 72    /* 64 + 8 */
#define SM_Q 0
#define SM_K (SM_Q + 128 * LDQ * 2)       /* 22528 */
#define SM_V (SM_K + 64 * LDQ * 2)        /* 33792 */
#define SM_P (SM_V + 80 * LDP * 2)        /* 45312 */
#define SM_TOT (SM_P + 128 * LDP * 2)     /* 63744 */

__global__ __launch_bounds__(256) void flash_mma()
{
    extern __shared__ char sm[];
    __half (*Q1s)[LDQ] = (__half(*)[LDQ])(sm + SM_Q);
    __half (*K1s)[LDQ] = (__half(*)[LDQ])(sm + SM_K);
    __half (*Vts)[LDP] = (__half(*)[LDP])(sm + SM_V);
    __half (*P1s)[LDP] = (__half(*)[LDP])(sm + SM_P);

    const int tid  = threadIdx.x;
    const int w    = tid >> 5;
    const int lane = tid & 31;
    const int h    = blockIdx.y;
    const int c    = blockIdx.z;
    const int q0   = c * CHUNK_L + blockIdx.x * 128;

#pragma unroll
    for (int i = 0; i < 5; i++) {
        int idx = tid + i * 256;
        int r = idx / 10, j = idx % 10;
        *(uint4*)&Q1s[r][j * 8] =
            *(const uint4*)&g_Q1[((size_t)(q0 + r) * HEADS + h) * HEAD_DIM + j * 8];
    }

    const int lrow = lane & 15;
    const int lcol = (lane >> 4) << 3;
    const uint32_t qAddr = smem_u32(&Q1s[w * 16 + lrow][lcol]);
    const uint32_t pAddr = smem_u32(&P1s[w * 16 + lrow][lcol]);
    uint32_t kAddr[4], vAddr[5];
#pragma unroll
    for (int np = 0; np < 4; np++)
        kAddr[np] = smem_u32(&K1s[np * 16 + lrow][lcol]);
#pragma unroll
    for (int np = 0; np < 5; np++)
        vAddr[np] = smem_u32(&Vts[np * 16 + lrow][lcol]);

    const int cr = lane >> 2;
    const int cc = (lane & 3) * 2;
    uint32_t* Prow0 = (uint32_t*)&P1s[w * 16 + cr][0];
    uint32_t* Prow1 = (uint32_t*)&P1s[w * 16 + cr + 8][0];

    float O[10][4];
#pragma unroll
    for (int nt = 0; nt < 10; nt++)
#pragma unroll
        for (int v = 0; v < 4; v++) O[nt][v] = 0.0f;
    float m0 = -1e30f, m1 = -1e30f, l0 = 0.0f, l1 = 0.0f;

    const size_t vBase = (size_t)(c * HEADS + h) * HEAD_DIM * CHUNK_L;

    for (int kt = 0; kt < CHUNK_L / 64; kt++) {
        const int kv0 = kt * 64;
        __syncthreads();
#pragma unroll
        for (int i = 0; i < 5; i++) {
            int idx = tid + i * 256;
            if (idx < 640) {
                int r = idx / 10, j = idx % 10;
                *(uint4*)&K1s[r][j * 8] =
                    *(const uint4*)&g_K1[((size_t)(c * CHUNK_L + kv0 + r) * HEADS + h) * HEAD_DIM + j * 8];
            } else {
                int vx = idx - 640;
                int d = vx >> 3, j = vx & 7;
                *(uint4*)&Vts[d][j * 8] =
                    *(const uint4*)&g_Vt[vBase + (size_t)d * CHUNK_L + kv0 + j * 8];
            }
        }
        __syncthreads();

        float s[8][4];
#pragma unroll
        for (int nt = 0; nt < 8; nt++)
#pragma unroll
            for (int v = 0; v < 4; v++) s[nt][v] = 0.0f;
#pragma unroll
        for (int ks = 0; ks < 5; ks++) {
            uint32_t af[4];
            ldsm_x4(af, qAddr + ks * 32);
            uint32_t bf[8][2];
#pragma unroll
            for (int np = 0; np < 4; np++) {
                uint32_t r[4];
                ldsm_x4(r, kAddr[np] + ks * 32);
                bf[2 * np][0]     = r[0]; bf[2 * np][1]     = r[2];
                bf[2 * np + 1][0] = r[1]; bf[2 * np + 1][1] = r[3];
            }
#pragma unroll
            for (int nt = 0; nt < 8; nt++)
                mma_16816(s[nt], af, bf[nt]);
        }

        float tm0 = -1e30f, tm1 = -1e30f;
#pragma unroll
        for (int nt = 0; nt < 8; nt++) {
            tm0 = fmaxf(tm0, fmaxf(s[nt][0], s[nt][1]));
            tm1 = fmaxf(tm1, fmaxf(s[nt][2], s[nt][3]));
        }
        tm0 = fmaxf(tm0, __shfl_xor_sync(0xffffffffu, tm0, 1));
        tm0 = fmaxf(tm0, __shfl_xor_sync(0xffffffffu, tm0, 2));
        tm1 = fmaxf(tm1, __shfl_xor_sync(0xffffffffu, tm1, 1));
        tm1 = fmaxf(tm1, __shfl_xor_sync(0xffffffffu, tm1, 2));
        const float nm0 = fmaxf(m0, tm0);
        const float nm1 = fmaxf(m1, tm1);
        const float a0 = __expf(m0 - nm0);
        const float a1 = __expf(m1 - nm1);
        m0 = nm0; m1 = nm1;

        float sum0 = 0.0f, sum1 = 0.0f;
#pragma unroll
        for (int nt = 0; nt < 8; nt++) {
            float p00 = __expf(s[nt][0] - nm0);
            float p01 = __expf(s[nt][1] - nm0);
            float p10 = __expf(s[nt][2] - nm1);
            float p11 = __expf(s[nt][3] - nm1);
            sum0 += p00 + p01;
            sum1 += p10 + p11;
            const int cw = (nt * 8 + cc) >> 1;
            Prow0[cw] = pack2h(__float2half_rn(p00), __float2half_rn(p01));
            Prow1[cw] = pack2h(__float2half_rn(p10), __float2half_rn(p11));
        }
        sum0 += __shfl_xor_sync(0xffffffffu, sum0, 1);
        sum0 += __shfl_xor_sync(0xffffffffu, sum0, 2);
        sum1 += __shfl_xor_sync(0xffffffffu, sum1, 1);
        sum1 += __shfl_xor_sync(0xffffffffu, sum1, 2);
        l0 = l0 * a0 + sum0;
        l1 = l1 * a1 + sum1;

#pragma unroll
        for (int nt = 0; nt < 10; nt++) {
            O[nt][0] *= a0; O[nt][1] *= a0;
            O[nt][2] *= a1; O[nt][3] *= a1;
        }
        __syncthreads();

#pragma unroll
        for (int ks = 0; ks < 4; ks++) {
            uint32_t af[4];
            ldsm_x4(af, pAddr + ks * 32);
            uint32_t bf[10][2];
#pragma unroll
            for (int np = 0; np < 5; np++) {
                uint32_t r[4];
                ldsm_x4(r, vAddr[np] + ks * 32);
                bf[2 * np][0]     = r[0]; bf[2 * np][1]     = r[2];
                bf[2 * np + 1][0] = r[1]; bf[2 * np + 1][1] = r[3];
            }
#pragma unroll
            for (int nt = 0; nt < 10; nt++)
                mma_16816(O[nt], af, bf[nt]);
        }
    }

    const float inv0 = 1.0f / l0;
    const float inv1 = 1.0f / l1;
    const int r0 = q0 + w * 16 + cr;
#pragma unroll
    for (int nt = 0; nt < 10; nt++) {
        const int col = h * HEAD_DIM + nt * 8 + cc;
        *(uint32_t*)&g_Ap[(size_t)r0 * HIDDEN + col] =
            pack2h(__float2half_rn(O[nt][0] * inv0),
                   __float2half_rn(O[nt][1] * inv0));
        *(uint32_t*)&g_Ap[(size_t)(r0 + 8) * HIDDEN + col] =
            pack2h(__float2half_rn(O[nt][2] * inv1),
                   __float2half_rn(O[nt][3] * inv1));
    }
}

// ---------------------------------------------------------------------------
extern "C" void kernel_launch(void* const* d_in, const int* in_sizes, int n_in,
                              void* d_out, int out_size)
{
    (void)in_sizes; (void)n_in; (void)out_size;
    const float* x      = (const float*)d_in[0];
    const float* cosp   = (const float*)d_in[1];
    const float* sinp   = (const float*)d_in[2];
    const float* w_qkv  = (const float*)d_in[3];
    const float* b_qkv  = (const float*)d_in[4];
    const float* w_proj = (const float*)d_in[5];
    const float* b_proj = (const float*)d_in[6];
    float* out = (float*)d_out;

    __half *Aq = nullptr, *Ap = nullptr, *Bq = nullptr, *Bp = nullptr;
    __half *QK16 = nullptr, *V16 = nullptr;
    cudaGetSymbolAddress((void**)&Aq,   g_Aq);
    cudaGetSymbolAddress((void**)&Ap,   g_Ap);
    cudaGetSymbolAddress((void**)&Bq,   g_Bq);
    cudaGetSymbolAddress((void**)&Bp,   g_Bp);
    cudaGetSymbolAddress((void**)&QK16, g_QK16);
    cudaGetSymbolAddress((void**)&V16,  g_V16);

    cudaFuncSetAttribute(gemm_fp16_mma,
                         cudaFuncAttributeMaxDynamicSharedMemorySize, GSMEM);
    cudaFuncSetAttribute(flash_mma,
                         cudaFuncAttributeMaxDynamicSharedMemorySize, SM_TOT);

    // conversions: both weights in one launch, then activations
    convert_Bb<<<dim3(QKVN / 32, HIDDEN / 32, 2), dim3(32, 8)>>>(
        w_qkv, w_proj, Bq, Bp);
    {
        int mk = TOTAL * HIDDEN;
        convert_A<<<(mk / 4 + 255) / 256, 256>>>(x, Aq, mk);
    }

    // 1) QKV projection -> q,k fp16 (g_QK16), v fp16 (g_V16)
    gemm_fp16_mma<<<dim3(QKVN / 128, TOTAL / 128), 128, GSMEM>>>(
        Aq, Bq, b_qkv, nullptr, QK16, V16, QKVN, HIDDEN);

    // 2) fused RoPE + V transpose
    rope_vtrans<<<RS_BLOCKS + VT_BLOCKS, 256>>>(cosp, sinp);

    // 3) flash attention (writes fp16 attn into g_Ap)
    flash_mma<<<dim3(CHUNK_L / 128, HEADS, NCHUNK), 256, SM_TOT>>>();

    // 4) output projection (fp32 out)
    gemm_fp16_mma<<<dim3(HIDDEN / 128, TOTAL / 128), 128, GSMEM>>>(
        Ap, Bp, b_proj, out, nullptr, nullptr, HIDDEN, HIDDEN);
}